// round 1
// baseline (speedup 1.0000x reference)
#include <cuda_runtime.h>

// Problem constants
#define BB 64
#define NN 64
#define CC 8
#define FF 256
#define KDIM 2048   // C*F
#define ODIM 2048   // OC*OF
#define MROWS 4160  // B + B*N rows of Z

// Scratch (device globals; no dynamic allocation allowed)
__device__ float g_w1s[FF];
__device__ float g_w2s[FF];
__device__ float g_s1[BB];
__device__ float g_w[BB * NN];
__device__ float g_t[BB * KDIM];
__device__ float g_adj[(size_t)BB * CC * FF * FF];   // 134 MB
__device__ float g_Z[(size_t)MROWS * KDIM];          // 34 MB

__device__ __forceinline__ float blockReduce256(float v) {
    __shared__ float sh[8];
    #pragma unroll
    for (int o = 16; o > 0; o >>= 1) v += __shfl_down_sync(0xffffffffu, v, o);
    int lane = threadIdx.x & 31, wid = threadIdx.x >> 5;
    if (lane == 0) sh[wid] = v;
    __syncthreads();
    if (wid == 0) {
        v = (lane < 8) ? sh[lane] : 0.f;
        #pragma unroll
        for (int o = 4; o > 0; o >>= 1) v += __shfl_down_sync(0xffffffffu, v, o);
    }
    return v;
}

// K0: column sums of W1/W2 (einsum over k collapses attention to a scalar weight)
__global__ void k_wsum(const float* __restrict__ W1, const float* __restrict__ W2) {
    int f = threadIdx.x;
    float a = 0.f, b = 0.f;
    #pragma unroll
    for (int k = 0; k < CC; k++) { a += W1[k * FF + f]; b += W2[k * FF + f]; }
    g_w1s[f] = a; g_w2s[f] = b;
}

// K1: s1[b] = sum_{c,f} x[b,c,f] * w1s[f]
__global__ void k_s1(const float* __restrict__ x) {
    int b = blockIdx.x;
    float acc = 0.f;
    for (int i = threadIdx.x; i < KDIM; i += 256)
        acc += x[b * KDIM + i] * g_w1s[i & (FF - 1)];
    acc = blockReduce256(acc);
    if (threadIdx.x == 0) g_s1[b] = acc;
}

// K2: w[b,n] = s1[b] * sum_{c,f} nb[b,n,c,f] * w2s[f]
__global__ void k_w(const float* __restrict__ nb) {
    int bn = blockIdx.x;
    const float* p = nb + (size_t)bn * KDIM;
    float acc = 0.f;
    for (int i = threadIdx.x; i < KDIM; i += 256)
        acc += p[i] * g_w2s[i & (FF - 1)];
    acc = blockReduce256(acc);
    if (threadIdx.x == 0) g_w[bn] = acc * g_s1[bn >> 6];
}

// K3: t[b,c,d] = sum_n nb[b,n,c,d] * w[b,n]
__global__ void k_t(const float* __restrict__ nb) {
    int b = blockIdx.x >> 3;
    int r = ((blockIdx.x & 7) << 8) | threadIdx.x;   // c*256+d within b
    __shared__ float sw[NN];
    if (threadIdx.x < NN) sw[threadIdx.x] = g_w[b * NN + threadIdx.x];
    __syncthreads();
    const float* p = nb + (size_t)b * NN * KDIM + r;
    float acc = 0.f;
    #pragma unroll 8
    for (int n = 0; n < NN; n++) acc += p[(size_t)n * KDIM] * sw[n];
    g_t[b * KDIM + r] = acc;
}

// K4: adj[b,c,a,d] = sgnroot(x_a t_d + x_d t_a) / (sum_c |sgnroot| + 1e-7)
// block = (a, b), threads over d. fadj is an outer product -> O(B*C*F^2) only.
__global__ void k_adj(const float* __restrict__ x) {
    int a = blockIdx.x, b = blockIdx.y;
    __shared__ float sxa[CC], sta[CC];
    int tid = threadIdx.x;
    if (tid < CC)            sxa[tid]      = x[b * KDIM + tid * FF + a];
    else if (tid < 2 * CC)   sta[tid - CC] = g_t[b * KDIM + (tid - CC) * FF + a];
    __syncthreads();
    int d = tid;
    float gg[CC];
    float den = 1e-7f;
    #pragma unroll
    for (int c = 0; c < CC; c++) {
        float xd = x[b * KDIM + c * FF + d];
        float td = g_t[b * KDIM + c * FF + d];
        float fa = sxa[c] * td + xd * sta[c];
        float s  = (fa > 0.f) ? 1.f : ((fa < 0.f) ? -1.f : 0.f);
        float g  = s * sqrtf(fmaxf(fabsf(fa), 1e-8f));
        gg[c] = g;
        den += fabsf(g);
    }
    float inv = 1.f / den;
    size_t base = ((size_t)(b * CC) * FF + a) * FF + d;
    #pragma unroll
    for (int c = 0; c < CC; c++)
        g_adj[base + (size_t)c * FF * FF] = gg[c] * inv;
}

// K5: zn[b,n,c,a] = sum_d adj[b,c,a,d] * nb[b,n,c,d]
// Batched GEMM per (b,c): (64n x 256d) @ (256d x 128a-tile). Micro-tile 4n x 8a.
__global__ __launch_bounds__(256) void k_zn(const float* __restrict__ nb) {
    int a0 = blockIdx.x * 128;
    int c  = blockIdx.y;
    int b  = blockIdx.z;
    __shared__ float sN[16][68];    // [dd][n], padded for 16B-aligned float4 rows
    __shared__ float sA[16][132];   // [dd][a]
    int tid = threadIdx.x;
    int tx = tid & 15, ty = tid >> 4;     // tx -> a-group, ty -> n-group
    float acc[4][8];
    #pragma unroll
    for (int i = 0; i < 4; i++)
        #pragma unroll
        for (int j = 0; j < 8; j++) acc[i][j] = 0.f;

    const float* nbase = nb + (size_t)b * NN * KDIM + c * FF;          // [n][d], stride KDIM
    const float* abase = g_adj + ((size_t)(b * CC + c) * FF + a0) * FF; // [a][d], stride FF

    int nrow = tid >> 2, nkq = (tid & 3) * 4;  // 64 rows x 4 cols each
    int arow = tid >> 1, akq = (tid & 1) * 8;  // 128 rows x 8 cols each

    for (int d0 = 0; d0 < FF; d0 += 16) {
        float4 v  = *(const float4*)(nbase + (size_t)nrow * KDIM + d0 + nkq);
        float4 w0 = *(const float4*)(abase + (size_t)arow * FF + d0 + akq);
        float4 w1 = *(const float4*)(abase + (size_t)arow * FF + d0 + akq + 4);
        __syncthreads();
        sN[nkq + 0][nrow] = v.x;  sN[nkq + 1][nrow] = v.y;
        sN[nkq + 2][nrow] = v.z;  sN[nkq + 3][nrow] = v.w;
        sA[akq + 0][arow] = w0.x; sA[akq + 1][arow] = w0.y;
        sA[akq + 2][arow] = w0.z; sA[akq + 3][arow] = w0.w;
        sA[akq + 4][arow] = w1.x; sA[akq + 5][arow] = w1.y;
        sA[akq + 6][arow] = w1.z; sA[akq + 7][arow] = w1.w;
        __syncthreads();
        #pragma unroll
        for (int dd = 0; dd < 16; dd++) {
            float rn[4], ra[8];
            *(float4*)rn       = *(const float4*)&sN[dd][ty * 4];
            *(float4*)ra       = *(const float4*)&sA[dd][tx * 8];
            *(float4*)(ra + 4) = *(const float4*)&sA[dd][tx * 8 + 4];
            #pragma unroll
            for (int i = 0; i < 4; i++)
                #pragma unroll
                for (int j = 0; j < 8; j++) acc[i][j] += rn[i] * ra[j];
        }
    }
    // Z row = 64 + b*64 + n, col = c*256 + a0 + a
    #pragma unroll
    for (int i = 0; i < 4; i++) {
        int n = ty * 4 + i;
        float* o = g_Z + (size_t)(BB + b * NN + n) * KDIM + c * FF + a0 + tx * 8;
        *(float4*)o       = *(float4*)&acc[i][0];
        *(float4*)(o + 4) = *(float4*)&acc[i][4];
    }
}

// K6: zx[b,c,a] = sum_d adj[b,c,a,d] * x[b,c,d]  -> Z rows 0..63
__global__ void k_zx(const float* __restrict__ x) {
    int c = blockIdx.x & 7, b = blockIdx.x >> 3;
    __shared__ float sx[FF];
    int tid = threadIdx.x;
    sx[tid] = x[b * KDIM + c * FF + tid];
    __syncthreads();
    int lane = tid & 31, w = tid >> 5;
    const float* ab = g_adj + (size_t)(b * CC + c) * FF * FF;
    for (int a = w; a < FF; a += 8) {
        const float* row = ab + (size_t)a * FF;
        float acc = 0.f;
        for (int d = lane; d < FF; d += 32) acc += row[d] * sx[d];
        #pragma unroll
        for (int o = 16; o > 0; o >>= 1) acc += __shfl_down_sync(0xffffffffu, acc, o);
        if (lane == 0) g_Z[(size_t)b * KDIM + c * FF + a] = acc;
    }
}

// K7: out = Z (4160 x 2048) @ Wc^T (2048 x 2048). Both K-contiguous row-major.
// 128x128 tile, 8x8 micro-tile, k-chunk 16.
__global__ __launch_bounds__(256) void k_gemm(const float* __restrict__ Wc,
                                              float* __restrict__ out) {
    __shared__ float sA[16][132];
    __shared__ float sB[16][132];
    int n0 = blockIdx.x * 128;
    int m0 = blockIdx.y * 128;
    int tid = threadIdx.x;
    int tx = tid & 15, ty = tid >> 4;
    int lr = tid >> 1, lk = (tid & 1) * 8;
    float acc[8][8];
    #pragma unroll
    for (int i = 0; i < 8; i++)
        #pragma unroll
        for (int j = 0; j < 8; j++) acc[i][j] = 0.f;

    for (int k0 = 0; k0 < KDIM; k0 += 16) {
        float4 a0, a1;
        int gm = m0 + lr;
        if (gm < MROWS) {
            const float* p = g_Z + (size_t)gm * KDIM + k0 + lk;
            a0 = *(const float4*)p; a1 = *(const float4*)(p + 4);
        } else {
            a0 = make_float4(0.f, 0.f, 0.f, 0.f); a1 = a0;
        }
        const float* q = Wc + (size_t)(n0 + lr) * KDIM + k0 + lk;
        float4 b0 = *(const float4*)q, b1 = *(const float4*)(q + 4);
        __syncthreads();
        sA[lk + 0][lr] = a0.x; sA[lk + 1][lr] = a0.y;
        sA[lk + 2][lr] = a0.z; sA[lk + 3][lr] = a0.w;
        sA[lk + 4][lr] = a1.x; sA[lk + 5][lr] = a1.y;
        sA[lk + 6][lr] = a1.z; sA[lk + 7][lr] = a1.w;
        sB[lk + 0][lr] = b0.x; sB[lk + 1][lr] = b0.y;
        sB[lk + 2][lr] = b0.z; sB[lk + 3][lr] = b0.w;
        sB[lk + 4][lr] = b1.x; sB[lk + 5][lr] = b1.y;
        sB[lk + 6][lr] = b1.z; sB[lk + 7][lr] = b1.w;
        __syncthreads();
        #pragma unroll
        for (int kk = 0; kk < 16; kk++) {
            float ra[8], rb[8];
            *(float4*)ra       = *(const float4*)&sA[kk][ty * 8];
            *(float4*)(ra + 4) = *(const float4*)&sA[kk][ty * 8 + 4];
            *(float4*)rb       = *(const float4*)&sB[kk][tx * 8];
            *(float4*)(rb + 4) = *(const float4*)&sB[kk][tx * 8 + 4];
            #pragma unroll
            for (int i = 0; i < 8; i++)
                #pragma unroll
                for (int j = 0; j < 8; j++) acc[i][j] += ra[i] * rb[j];
        }
    }
    #pragma unroll
    for (int i = 0; i < 8; i++) {
        int gm = m0 + ty * 8 + i;
        if (gm < MROWS) {
            float* o = out + (size_t)gm * ODIM + n0 + tx * 8;
            *(float4*)o       = *(float4*)&acc[i][0];
            *(float4*)(o + 4) = *(float4*)&acc[i][4];
        }
    }
}

extern "C" void kernel_launch(void* const* d_in, const int* in_sizes, int n_in,
                              void* d_out, int out_size) {
    const float* x  = (const float*)d_in[0];  // (64,8,256)
    const float* nb = (const float*)d_in[1];  // (64,64,8,256)
    const float* W1 = (const float*)d_in[2];  // (8,256)
    const float* W2 = (const float*)d_in[3];  // (8,256)
    const float* Wc = (const float*)d_in[4];  // (2048,8,256)
    float* out = (float*)d_out;               // 64*2048 (x_out) then 64*64*2048 (n_out)

    k_wsum<<<1, 256>>>(W1, W2);
    k_s1<<<BB, 256>>>(x);
    k_w<<<BB * NN, 256>>>(nb);
    k_t<<<512, 256>>>(nb);
    k_adj<<<dim3(FF, BB), 256>>>(x);
    k_zn<<<dim3(2, CC, BB), 256>>>(nb);
    k_zx<<<512, 256>>>(x);
    k_gemm<<<dim3(16, 33), 256>>>(Wc, out);
}

// round 3
// speedup vs baseline: 1.8756x; 1.8756x over previous
#include <cuda_runtime.h>
#include <cuda_bf16.h>
#include <cstdint>

// Problem constants
#define BB 64
#define NN 64
#define CC 8
#define FF 256
#define KDIM 2048   // C*F
#define ODIM 2048   // OC*OF
#define MROWS 4160  // B + B*N rows of Z
#define MPAD 4224   // padded to 33*128

// Scratch (device globals; no dynamic allocation allowed)
__device__ float g_w1s[FF];
__device__ float g_w2s[FF];
__device__ float g_s1[BB];
__device__ float g_w[BB * NN];
__device__ float g_t[BB * KDIM];
__device__ float g_adj[(size_t)BB * CC * FF * FF];   // 134 MB
__device__ float g_Z[(size_t)MROWS * KDIM];          // 34 MB
// bf16 hi/lo splits for the tensor-core GEMM
__device__ __nv_bfloat16 g_Zh[(size_t)MPAD * KDIM];
__device__ __nv_bfloat16 g_Zl[(size_t)MPAD * KDIM];
__device__ __nv_bfloat16 g_Wh[(size_t)ODIM * KDIM];
__device__ __nv_bfloat16 g_Wl[(size_t)ODIM * KDIM];

__device__ __forceinline__ float blockReduce256(float v) {
    __shared__ float sh[8];
    #pragma unroll
    for (int o = 16; o > 0; o >>= 1) v += __shfl_down_sync(0xffffffffu, v, o);
    int lane = threadIdx.x & 31, wid = threadIdx.x >> 5;
    if (lane == 0) sh[wid] = v;
    __syncthreads();
    if (wid == 0) {
        v = (lane < 8) ? sh[lane] : 0.f;
        #pragma unroll
        for (int o = 4; o > 0; o >>= 1) v += __shfl_down_sync(0xffffffffu, v, o);
    }
    return v;
}

// K0: column sums of W1/W2
__global__ void k_wsum(const float* __restrict__ W1, const float* __restrict__ W2) {
    int f = threadIdx.x;
    float a = 0.f, b = 0.f;
    #pragma unroll
    for (int k = 0; k < CC; k++) { a += W1[k * FF + f]; b += W2[k * FF + f]; }
    g_w1s[f] = a; g_w2s[f] = b;
}

// K1: s1[b] = sum_{c,f} x[b,c,f] * w1s[f]
__global__ void k_s1(const float* __restrict__ x) {
    int b = blockIdx.x;
    float acc = 0.f;
    for (int i = threadIdx.x; i < KDIM; i += 256)
        acc += x[b * KDIM + i] * g_w1s[i & (FF - 1)];
    acc = blockReduce256(acc);
    if (threadIdx.x == 0) g_s1[b] = acc;
}

// K2: w[b,n] = s1[b] * sum_{c,f} nb[b,n,c,f] * w2s[f]
__global__ void k_w(const float* __restrict__ nb) {
    int bn = blockIdx.x;
    const float* p = nb + (size_t)bn * KDIM;
    float acc = 0.f;
    for (int i = threadIdx.x; i < KDIM; i += 256)
        acc += p[i] * g_w2s[i & (FF - 1)];
    acc = blockReduce256(acc);
    if (threadIdx.x == 0) g_w[bn] = acc * g_s1[bn >> 6];
}

// K3: t[b,c,d] = sum_n nb[b,n,c,d] * w[b,n]
__global__ void k_t(const float* __restrict__ nb) {
    int b = blockIdx.x >> 3;
    int r = ((blockIdx.x & 7) << 8) | threadIdx.x;
    __shared__ float sw[NN];
    if (threadIdx.x < NN) sw[threadIdx.x] = g_w[b * NN + threadIdx.x];
    __syncthreads();
    const float* p = nb + (size_t)b * NN * KDIM + r;
    float acc = 0.f;
    #pragma unroll 8
    for (int n = 0; n < NN; n++) acc += p[(size_t)n * KDIM] * sw[n];
    g_t[b * KDIM + r] = acc;
}

// K4: adj[b,c,a,d] = sgnroot(x_a t_d + x_d t_a) / (sum_c |sgnroot| + 1e-7)
__global__ void k_adj(const float* __restrict__ x) {
    int a = blockIdx.x, b = blockIdx.y;
    __shared__ float sxa[CC], sta[CC];
    int tid = threadIdx.x;
    if (tid < CC)            sxa[tid]      = x[b * KDIM + tid * FF + a];
    else if (tid < 2 * CC)   sta[tid - CC] = g_t[b * KDIM + (tid - CC) * FF + a];
    __syncthreads();
    int d = tid;
    float gg[CC];
    float den = 1e-7f;
    #pragma unroll
    for (int c = 0; c < CC; c++) {
        float xd = x[b * KDIM + c * FF + d];
        float td = g_t[b * KDIM + c * FF + d];
        float fa = sxa[c] * td + xd * sta[c];
        float s  = (fa > 0.f) ? 1.f : ((fa < 0.f) ? -1.f : 0.f);
        float g  = s * sqrtf(fmaxf(fabsf(fa), 1e-8f));
        gg[c] = g;
        den += fabsf(g);
    }
    float inv = 1.f / den;
    size_t base = ((size_t)(b * CC) * FF + a) * FF + d;
    #pragma unroll
    for (int c = 0; c < CC; c++)
        g_adj[base + (size_t)c * FF * FF] = gg[c] * inv;
}

// K5: zn[b,n,c,a] = sum_d adj[b,c,a,d] * nb[b,n,c,d]
__global__ __launch_bounds__(256) void k_zn(const float* __restrict__ nb) {
    int a0 = blockIdx.x * 128;
    int c  = blockIdx.y;
    int b  = blockIdx.z;
    __shared__ float sN[16][68];
    __shared__ float sA[16][132];
    int tid = threadIdx.x;
    int tx = tid & 15, ty = tid >> 4;
    float acc[4][8];
    #pragma unroll
    for (int i = 0; i < 4; i++)
        #pragma unroll
        for (int j = 0; j < 8; j++) acc[i][j] = 0.f;

    const float* nbase = nb + (size_t)b * NN * KDIM + c * FF;
    const float* abase = g_adj + ((size_t)(b * CC + c) * FF + a0) * FF;

    int nrow = tid >> 2, nkq = (tid & 3) * 4;
    int arow = tid >> 1, akq = (tid & 1) * 8;

    for (int d0 = 0; d0 < FF; d0 += 16) {
        float4 v  = *(const float4*)(nbase + (size_t)nrow * KDIM + d0 + nkq);
        float4 w0 = *(const float4*)(abase + (size_t)arow * FF + d0 + akq);
        float4 w1 = *(const float4*)(abase + (size_t)arow * FF + d0 + akq + 4);
        __syncthreads();
        sN[nkq + 0][nrow] = v.x;  sN[nkq + 1][nrow] = v.y;
        sN[nkq + 2][nrow] = v.z;  sN[nkq + 3][nrow] = v.w;
        sA[akq + 0][arow] = w0.x; sA[akq + 1][arow] = w0.y;
        sA[akq + 2][arow] = w0.z; sA[akq + 3][arow] = w0.w;
        sA[akq + 4][arow] = w1.x; sA[akq + 5][arow] = w1.y;
        sA[akq + 6][arow] = w1.z; sA[akq + 7][arow] = w1.w;
        __syncthreads();
        #pragma unroll
        for (int dd = 0; dd < 16; dd++) {
            float rn[4], ra[8];
            *(float4*)rn       = *(const float4*)&sN[dd][ty * 4];
            *(float4*)ra       = *(const float4*)&sA[dd][tx * 8];
            *(float4*)(ra + 4) = *(const float4*)&sA[dd][tx * 8 + 4];
            #pragma unroll
            for (int i = 0; i < 4; i++)
                #pragma unroll
                for (int j = 0; j < 8; j++) acc[i][j] += rn[i] * ra[j];
        }
    }
    #pragma unroll
    for (int i = 0; i < 4; i++) {
        int n = ty * 4 + i;
        float* o = g_Z + (size_t)(BB + b * NN + n) * KDIM + c * FF + a0 + tx * 8;
        *(float4*)o       = *(float4*)&acc[i][0];
        *(float4*)(o + 4) = *(float4*)&acc[i][4];
    }
}

// K6: zx[b,c,a] = sum_d adj[b,c,a,d] * x[b,c,d]  -> Z rows 0..63
__global__ void k_zx(const float* __restrict__ x) {
    int c = blockIdx.x & 7, b = blockIdx.x >> 3;
    __shared__ float sx[FF];
    int tid = threadIdx.x;
    sx[tid] = x[b * KDIM + c * FF + tid];
    __syncthreads();
    int lane = tid & 31, w = tid >> 5;
    const float* ab = g_adj + (size_t)(b * CC + c) * FF * FF;
    for (int a = w; a < FF; a += 8) {
        const float* row = ab + (size_t)a * FF;
        float acc = 0.f;
        for (int d = lane; d < FF; d += 32) acc += row[d] * sx[d];
        #pragma unroll
        for (int o = 16; o > 0; o >>= 1) acc += __shfl_down_sync(0xffffffffu, acc, o);
        if (lane == 0) g_Z[(size_t)b * KDIM + c * FF + a] = acc;
    }
}

// ---------- bf16 hi/lo split conversion ----------
__device__ __forceinline__ void cvt_row(const float* __restrict__ src,
                                        __nv_bfloat16* __restrict__ hi,
                                        __nv_bfloat16* __restrict__ lo,
                                        size_t row, bool valid) {
    int c0 = threadIdx.x * 8;
    __align__(16) __nv_bfloat16 h[8], l[8];
    if (valid) {
        const float4* p = (const float4*)(src + row * KDIM + c0);
        float4 v0 = p[0], v1 = p[1];
        float vv[8] = {v0.x, v0.y, v0.z, v0.w, v1.x, v1.y, v1.z, v1.w};
        #pragma unroll
        for (int i = 0; i < 8; i++) {
            h[i] = __float2bfloat16(vv[i]);
            l[i] = __float2bfloat16(vv[i] - __bfloat162float(h[i]));
        }
    } else {
        #pragma unroll
        for (int i = 0; i < 8; i++) { h[i] = __float2bfloat16(0.f); l[i] = h[i]; }
    }
    *(uint4*)(hi + row * KDIM + c0) = *(uint4*)&h[0];
    *(uint4*)(lo + row * KDIM + c0) = *(uint4*)&l[0];
}

__global__ void k_cvt_W(const float* __restrict__ Wc) {
    cvt_row(Wc, g_Wh, g_Wl, blockIdx.x, true);
}
__global__ void k_cvt_Z() {
    cvt_row(g_Z, g_Zh, g_Zl, blockIdx.x, blockIdx.x < MROWS);
}

// ---------- warp-MMA helpers (sm_80+ PTX only; no 'a'-suffix features) ----------
__device__ __forceinline__ uint32_t smem_u32(const void* p) {
    uint32_t a;
    asm("{ .reg .u64 t; cvta.to.shared.u64 t, %1; cvt.u32.u64 %0, t; }"
        : "=r"(a) : "l"(p));
    return a;
}
__device__ __forceinline__ void cp16(uint32_t s, const void* g) {
    asm volatile("cp.async.cg.shared.global [%0], [%1], 16;" :: "r"(s), "l"(g) : "memory");
}
__device__ __forceinline__ void ldsm4(uint32_t* r, uint32_t addr) {
    asm volatile("ldmatrix.sync.aligned.m8n8.x4.shared.b16 {%0,%1,%2,%3}, [%4];"
                 : "=r"(r[0]), "=r"(r[1]), "=r"(r[2]), "=r"(r[3]) : "r"(addr));
}
__device__ __forceinline__ void mma16816(float* c, const uint32_t* a, const uint32_t* b) {
    asm volatile(
        "mma.sync.aligned.m16n8k16.row.col.f32.bf16.bf16.f32 "
        "{%0,%1,%2,%3}, {%4,%5,%6,%7}, {%8,%9}, {%0,%1,%2,%3};"
        : "+f"(c[0]), "+f"(c[1]), "+f"(c[2]), "+f"(c[3])
        : "r"(a[0]), "r"(a[1]), "r"(a[2]), "r"(a[3]), "r"(b[0]), "r"(b[1]));
}

// K7: out = Z(4224x2048 pad) @ Wc^T(2048x2048), bf16 3-term split on mma.sync.
// CTA tile 128x128, K-chunk 32, 3-stage cp.async pipeline, 8 warps of 64x32.
#define NST 3
#define ROWB 80            // 32 bf16 + 8 pad -> conflict-free ldmatrix
#define TILE_B (128 * ROWB)  // 10240
#define STAGE_B (4 * TILE_B) // Ah, Al, Bh, Bl
#define GEMM_SMEM (NST * STAGE_B)  // 122880

__device__ __forceinline__ void g_load_stage(char* smembase, int st, int kc,
                                             int tid, int m0, int n0) {
    uint32_t so_base = smem_u32(smembase) + st * STAGE_B;
    #pragma unroll
    for (int t = 0; t < 2; t++) {
        int idx = tid + (t << 8);             // 0..511
        int row = idx >> 2, seg = idx & 3;
        size_t gA = (size_t)(m0 + row) * KDIM + (kc << 5) + (seg << 3);
        size_t gB = (size_t)(n0 + row) * KDIM + (kc << 5) + (seg << 3);
        uint32_t so = so_base + row * ROWB + (seg << 4);
        cp16(so,              g_Zh + gA);
        cp16(so + TILE_B,     g_Zl + gA);
        cp16(so + 2 * TILE_B, g_Wh + gB);
        cp16(so + 3 * TILE_B, g_Wl + gB);
    }
}

__global__ __launch_bounds__(256, 1) void k_gemm_mma(float* __restrict__ out) {
    extern __shared__ char sm[];
    uint32_t sbase = smem_u32(sm);
    int tid = threadIdx.x;
    int lane = tid & 31, wid = tid >> 5;
    int m0 = blockIdx.y << 7, n0 = blockIdx.x << 7;
    int wm = (wid >> 2) << 6;      // warp m offset: 0 / 64
    int wn = (wid & 3) << 5;       // warp n offset: 0,32,64,96

    float c[4][4][4];
    #pragma unroll
    for (int i = 0; i < 4; i++)
        #pragma unroll
        for (int j = 0; j < 4; j++)
            #pragma unroll
            for (int q = 0; q < 4; q++) c[i][j][q] = 0.f;

    // precomputed ldmatrix lane offsets
    int a_row = wm + ((lane >> 3) & 1) * 8 + (lane & 7);
    int a_kof = (lane >> 4) * 8;
    int b_row = wn + ((lane >> 4) & 1) * 8 + (lane & 7);
    int b_kof = ((lane >> 3) & 1) * 8;

    g_load_stage(sm, 0, 0, tid, m0, n0);
    asm volatile("cp.async.commit_group;" ::: "memory");
    g_load_stage(sm, 1, 1, tid, m0, n0);
    asm volatile("cp.async.commit_group;" ::: "memory");

    for (int kc = 0; kc < 64; kc++) {
        asm volatile("cp.async.wait_group 1;" ::: "memory");
        __syncthreads();
        if (kc + 2 < 64) g_load_stage(sm, (kc + 2) % NST, kc + 2, tid, m0, n0);
        asm volatile("cp.async.commit_group;" ::: "memory");

        uint32_t sA  = sbase + (kc % NST) * STAGE_B;
        uint32_t sAl = sA + TILE_B;
        uint32_t sB  = sA + 2 * TILE_B;
        uint32_t sBl = sA + 3 * TILE_B;
        #pragma unroll
        for (int kk = 0; kk < 2; kk++) {
            int kb = kk << 4;
            uint32_t ah[4][4], al[4][4], bh[2][4], bl[2][4];
            uint32_t aofs = a_row * ROWB + (kb + a_kof) * 2;
            #pragma unroll
            for (int mt = 0; mt < 4; mt++) {
                ldsm4(ah[mt], sA  + aofs + mt * 16 * ROWB);
                ldsm4(al[mt], sAl + aofs + mt * 16 * ROWB);
            }
            uint32_t bofs = b_row * ROWB + (kb + b_kof) * 2;
            #pragma unroll
            for (int np = 0; np < 2; np++) {
                ldsm4(bh[np], sB  + bofs + np * 16 * ROWB);
                ldsm4(bl[np], sBl + bofs + np * 16 * ROWB);
            }
            #pragma unroll
            for (int mt = 0; mt < 4; mt++)
                #pragma unroll
                for (int j = 0; j < 4; j++) {
                    const uint32_t* pbh = &bh[j >> 1][(j & 1) * 2];
                    const uint32_t* pbl = &bl[j >> 1][(j & 1) * 2];
                    mma16816(c[mt][j], ah[mt], pbh);
                    mma16816(c[mt][j], ah[mt], pbl);
                    mma16816(c[mt][j], al[mt], pbh);
                }
        }
        __syncthreads();
    }

    // epilogue: C frag rows = lane>>2 (+8), cols = (lane&3)*2 (+1)
    #pragma unroll
    for (int mt = 0; mt < 4; mt++) {
        int r0 = m0 + wm + mt * 16 + (lane >> 2);
        #pragma unroll
        for (int j = 0; j < 4; j++) {
            int col = n0 + wn + j * 8 + (lane & 3) * 2;
            if (r0 < MROWS)
                *(float2*)(out + (size_t)r0 * ODIM + col) =
                    make_float2(c[mt][j][0], c[mt][j][1]);
            if (r0 + 8 < MROWS)
                *(float2*)(out + (size_t)(r0 + 8) * ODIM + col) =
                    make_float2(c[mt][j][2], c[mt][j][3]);
        }
    }
}

extern "C" void kernel_launch(void* const* d_in, const int* in_sizes, int n_in,
                              void* d_out, int out_size) {
    const float* x  = (const float*)d_in[0];  // (64,8,256)
    const float* nb = (const float*)d_in[1];  // (64,64,8,256)
    const float* W1 = (const float*)d_in[2];  // (8,256)
    const float* W2 = (const float*)d_in[3];  // (8,256)
    const float* Wc = (const float*)d_in[4];  // (2048,8,256)
    float* out = (float*)d_out;

    static bool attr_set = false;
    if (!attr_set) {
        cudaFuncSetAttribute(k_gemm_mma, cudaFuncAttributeMaxDynamicSharedMemorySize,
                             GEMM_SMEM);
        attr_set = true;
    }

    k_wsum<<<1, 256>>>(W1, W2);
    k_cvt_W<<<ODIM, 256>>>(Wc);
    k_s1<<<BB, 256>>>(x);
    k_w<<<BB * NN, 256>>>(nb);
    k_t<<<512, 256>>>(nb);
    k_adj<<<dim3(FF, BB), 256>>>(x);
    k_zn<<<dim3(2, CC, BB), 256>>>(nb);
    k_zx<<<512, 256>>>(x);
    k_cvt_Z<<<MPAD, 256>>>();
    k_gemm_mma<<<dim3(16, 33), 256, GEMM_SMEM>>>(out);
}

// round 4
// speedup vs baseline: 2.3277x; 1.2411x over previous
#include <cuda_runtime.h>
#include <cuda_bf16.h>
#include <cstdint>

// Problem constants
#define BB 64
#define NN 64
#define CC 8
#define FF 256
#define KDIM 2048   // C*F
#define ODIM 2048   // OC*OF
#define MROWS 4160  // B + B*N rows of Z
#define MPAD 4224   // padded to 33*128

// Scratch (device globals; no dynamic allocation allowed)
__device__ float g_w1s[FF];
__device__ float g_w2s[FF];
__device__ float g_s1[BB];
__device__ float g_w[BB * NN];
__device__ float g_t[BB * KDIM];
// adj in bf16 hi/lo split (written directly by k_adj)
__device__ __nv_bfloat16 g_adjh[(size_t)BB * CC * FF * FF];  // 67 MB
__device__ __nv_bfloat16 g_adjl[(size_t)BB * CC * FF * FF];  // 67 MB
// A-operand for znx GEMM: per b, 80 rows (64 neighbors, x, 15 pad) x KDIM
__device__ __nv_bfloat16 g_nxh[(size_t)BB * 80 * KDIM];
__device__ __nv_bfloat16 g_nxl[(size_t)BB * 80 * KDIM];
// bf16 hi/lo splits for the big GEMM
__device__ __nv_bfloat16 g_Zh[(size_t)MPAD * KDIM];
__device__ __nv_bfloat16 g_Zl[(size_t)MPAD * KDIM];
__device__ __nv_bfloat16 g_Wh[(size_t)ODIM * KDIM];
__device__ __nv_bfloat16 g_Wl[(size_t)ODIM * KDIM];

__device__ __forceinline__ float blockReduce256(float v) {
    __shared__ float sh[8];
    #pragma unroll
    for (int o = 16; o > 0; o >>= 1) v += __shfl_down_sync(0xffffffffu, v, o);
    int lane = threadIdx.x & 31, wid = threadIdx.x >> 5;
    if (lane == 0) sh[wid] = v;
    __syncthreads();
    if (wid == 0) {
        v = (lane < 8) ? sh[lane] : 0.f;
        #pragma unroll
        for (int o = 4; o > 0; o >>= 1) v += __shfl_down_sync(0xffffffffu, v, o);
    }
    return v;
}

// K0: column sums of W1/W2
__global__ void k_wsum(const float* __restrict__ W1, const float* __restrict__ W2) {
    int f = threadIdx.x;
    float a = 0.f, b = 0.f;
    #pragma unroll
    for (int k = 0; k < CC; k++) { a += W1[k * FF + f]; b += W2[k * FF + f]; }
    g_w1s[f] = a; g_w2s[f] = b;
}

// K1: s1[b] = sum_{c,f} x[b,c,f] * w1s[f]
__global__ void k_s1(const float* __restrict__ x) {
    int b = blockIdx.x;
    float acc = 0.f;
    for (int i = threadIdx.x; i < KDIM; i += 256)
        acc += x[b * KDIM + i] * g_w1s[i & (FF - 1)];
    acc = blockReduce256(acc);
    if (threadIdx.x == 0) g_s1[b] = acc;
}

// K2: w[b,n] = s1[b] * sum_{c,f} nb[b,n,c,f] * w2s[f]
__global__ void k_w(const float* __restrict__ nb) {
    int bn = blockIdx.x;
    const float* p = nb + (size_t)bn * KDIM;
    float acc = 0.f;
    for (int i = threadIdx.x; i < KDIM; i += 256)
        acc += p[i] * g_w2s[i & (FF - 1)];
    acc = blockReduce256(acc);
    if (threadIdx.x == 0) g_w[bn] = acc * g_s1[bn >> 6];
}

// K3: t[b,c,d] = sum_n nb[b,n,c,d] * w[b,n]
__global__ void k_t(const float* __restrict__ nb) {
    int b = blockIdx.x >> 3;
    int r = ((blockIdx.x & 7) << 8) | threadIdx.x;
    __shared__ float sw[NN];
    if (threadIdx.x < NN) sw[threadIdx.x] = g_w[b * NN + threadIdx.x];
    __syncthreads();
    const float* p = nb + (size_t)b * NN * KDIM + r;
    float acc = 0.f;
    #pragma unroll 8
    for (int n = 0; n < NN; n++) acc += p[(size_t)n * KDIM] * sw[n];
    g_t[b * KDIM + r] = acc;
}

// K4: adj[b,c,a,d] = sgnroot(x_a t_d + x_d t_a) / (sum_c |sgnroot| + 1e-7)
// Writes bf16 hi/lo split directly.
__global__ void k_adj(const float* __restrict__ x) {
    int a = blockIdx.x, b = blockIdx.y;
    __shared__ float sxa[CC], sta[CC];
    int tid = threadIdx.x;
    if (tid < CC)            sxa[tid]      = x[b * KDIM + tid * FF + a];
    else if (tid < 2 * CC)   sta[tid - CC] = g_t[b * KDIM + (tid - CC) * FF + a];
    __syncthreads();
    int d = tid;
    float gg[CC];
    float den = 1e-7f;
    #pragma unroll
    for (int c = 0; c < CC; c++) {
        float xd = x[b * KDIM + c * FF + d];
        float td = g_t[b * KDIM + c * FF + d];
        float fa = sxa[c] * td + xd * sta[c];
        float s  = (fa > 0.f) ? 1.f : ((fa < 0.f) ? -1.f : 0.f);
        float g  = s * sqrtf(fmaxf(fabsf(fa), 1e-8f));
        gg[c] = g;
        den += fabsf(g);
    }
    float inv = 1.f / den;
    size_t base = ((size_t)(b * CC) * FF + a) * FF + d;
    #pragma unroll
    for (int c = 0; c < CC; c++) {
        float v = gg[c] * inv;
        __nv_bfloat16 h = __float2bfloat16(v);
        __nv_bfloat16 l = __float2bfloat16(v - __bfloat162float(h));
        g_adjh[base + (size_t)c * FF * FF] = h;
        g_adjl[base + (size_t)c * FF * FF] = l;
    }
}

// ---------- bf16 hi/lo split helpers ----------
__device__ __forceinline__ void split8(const float* vv, __nv_bfloat16* h, __nv_bfloat16* l) {
    #pragma unroll
    for (int i = 0; i < 8; i++) {
        h[i] = __float2bfloat16(vv[i]);
        l[i] = __float2bfloat16(vv[i] - __bfloat162float(h[i]));
    }
}

__global__ void k_cvt_W(const float* __restrict__ Wc) {
    size_t row = blockIdx.x;
    int c0 = threadIdx.x * 8;
    const float4* p = (const float4*)(Wc + row * KDIM + c0);
    float4 v0 = p[0], v1 = p[1];
    float vv[8] = {v0.x, v0.y, v0.z, v0.w, v1.x, v1.y, v1.z, v1.w};
    __align__(16) __nv_bfloat16 h[8], l[8];
    split8(vv, h, l);
    *(uint4*)(g_Wh + row * KDIM + c0) = *(uint4*)&h[0];
    *(uint4*)(g_Wl + row * KDIM + c0) = *(uint4*)&l[0];
}

// Build the 80-row A-operand for znx: rows 0..63 = neighbors, 64 = x, 65..79 = 0
__global__ void k_cvt_nx(const float* __restrict__ x, const float* __restrict__ nb) {
    int r = blockIdx.x, b = blockIdx.y;
    int c0 = threadIdx.x * 8;
    size_t orow = ((size_t)b * 80 + r) * KDIM + c0;
    __align__(16) __nv_bfloat16 h[8], l[8];
    if (r <= 64) {
        const float* src = (r < 64) ? nb + ((size_t)b * NN + r) * KDIM
                                    : x + (size_t)b * KDIM;
        const float4* p = (const float4*)(src + c0);
        float4 v0 = p[0], v1 = p[1];
        float vv[8] = {v0.x, v0.y, v0.z, v0.w, v1.x, v1.y, v1.z, v1.w};
        split8(vv, h, l);
    } else {
        #pragma unroll
        for (int i = 0; i < 8; i++) { h[i] = __float2bfloat16(0.f); l[i] = h[i]; }
    }
    *(uint4*)(g_nxh + orow) = *(uint4*)&h[0];
    *(uint4*)(g_nxl + orow) = *(uint4*)&l[0];
}

// Zero the pad rows MROWS..MPAD of Zh/Zl (read by the big GEMM)
__global__ void k_zero_pad() {
    size_t row = MROWS + blockIdx.x;
    uint4 z = make_uint4(0, 0, 0, 0);
    *(uint4*)(g_Zh + row * KDIM + threadIdx.x * 8) = z;
    *(uint4*)(g_Zl + row * KDIM + threadIdx.x * 8) = z;
}

// ---------- warp-MMA helpers (sm_80+ PTX only) ----------
__device__ __forceinline__ uint32_t smem_u32(const void* p) {
    uint32_t a;
    asm("{ .reg .u64 t; cvta.to.shared.u64 t, %1; cvt.u32.u64 %0, t; }"
        : "=r"(a) : "l"(p));
    return a;
}
__device__ __forceinline__ void cp16(uint32_t s, const void* g) {
    asm volatile("cp.async.cg.shared.global [%0], [%1], 16;" :: "r"(s), "l"(g) : "memory");
}
__device__ __forceinline__ void ldsm4(uint32_t* r, uint32_t addr) {
    asm volatile("ldmatrix.sync.aligned.m8n8.x4.shared.b16 {%0,%1,%2,%3}, [%4];"
                 : "=r"(r[0]), "=r"(r[1]), "=r"(r[2]), "=r"(r[3]) : "r"(addr));
}
__device__ __forceinline__ void mma16816(float* c, const uint32_t* a, const uint32_t* b) {
    asm volatile(
        "mma.sync.aligned.m16n8k16.row.col.f32.bf16.bf16.f32 "
        "{%0,%1,%2,%3}, {%4,%5,%6,%7}, {%8,%9}, {%0,%1,%2,%3};"
        : "+f"(c[0]), "+f"(c[1]), "+f"(c[2]), "+f"(c[3])
        : "r"(a[0]), "r"(a[1]), "r"(a[2]), "r"(a[3]), "r"(b[0]), "r"(b[1]));
}

// ====================== K5: fused zn+zx tensor GEMM ======================
// Per (b,c): C[n=80, a=256] = NbX[80 x 256k] @ Adj[a=256 x 256k]^T, 3-term split.
// 8 warps: each covers full M=80 (5 m16 frags) x N=32. K-chunk 32, 2-stage.
#define ZROWB 80
#define ZA_TILE (80 * ZROWB)       // 6400
#define ZB_TILE (256 * ZROWB)      // 20480
#define ZSTAGE (2 * (ZA_TILE + ZB_TILE))  // 53760
#define ZNX_SMEM (2 * ZSTAGE)      // 107520

__device__ __forceinline__ void znx_load(char* smbase, int st, int kc,
                                         int tid, int b, int c) {
    uint32_t so = smem_u32(smbase) + st * ZSTAGE;
    int kb = kc << 5;
    #pragma unroll
    for (int t = 0; t < 2; t++) {
        int idx = tid + (t << 8);
        if (idx < 320) {
            int r = idx >> 2, s = idx & 3;
            size_t g = ((size_t)b * 80 + r) * KDIM + c * FF + kb + s * 8;
            uint32_t d = so + r * ZROWB + (s << 4);
            cp16(d, g_nxh + g);
            cp16(d + ZA_TILE, g_nxl + g);
        }
    }
    #pragma unroll
    for (int t = 0; t < 4; t++) {
        int idx = tid + (t << 8);
        int a = idx >> 2, s = idx & 3;
        size_t g = (((size_t)(b * CC + c)) * FF + a) * FF + kb + s * 8;
        uint32_t d = so + 2 * ZA_TILE + a * ZROWB + (s << 4);
        cp16(d, g_adjh + g);
        cp16(d + ZB_TILE, g_adjl + g);
    }
}

__global__ __launch_bounds__(256, 1) void k_znx() {
    extern __shared__ char sm[];
    uint32_t sbase = smem_u32(sm);
    int tid = threadIdx.x;
    int lane = tid & 31, wid = tid >> 5;
    int c = blockIdx.x, b = blockIdx.y;
    int wn = wid << 5;

    float acc[5][4][4];
    #pragma unroll
    for (int i = 0; i < 5; i++)
        #pragma unroll
        for (int j = 0; j < 4; j++)
            #pragma unroll
            for (int q = 0; q < 4; q++) acc[i][j][q] = 0.f;

    int a_row = ((lane >> 3) & 1) * 8 + (lane & 7);
    int a_kof = (lane >> 4) * 8;
    int b_row = wn + ((lane >> 4) & 1) * 8 + (lane & 7);
    int b_kof = ((lane >> 3) & 1) * 8;

    znx_load(sm, 0, 0, tid, b, c);
    asm volatile("cp.async.commit_group;" ::: "memory");

    for (int kc = 0; kc < 8; kc++) {
        if (kc < 7) {
            znx_load(sm, (kc + 1) & 1, kc + 1, tid, b, c);
            asm volatile("cp.async.commit_group;" ::: "memory");
            asm volatile("cp.async.wait_group 1;" ::: "memory");
        } else {
            asm volatile("cp.async.wait_group 0;" ::: "memory");
        }
        __syncthreads();
        uint32_t sA  = sbase + (kc & 1) * ZSTAGE;
        uint32_t sAl = sA + ZA_TILE;
        uint32_t sB  = sA + 2 * ZA_TILE;
        uint32_t sBl = sB + ZB_TILE;
        #pragma unroll
        for (int kk = 0; kk < 2; kk++) {
            int kb = kk << 4;
            uint32_t ah[5][4], al[5][4], bh[2][4], bl[2][4];
            uint32_t aofs = a_row * ZROWB + (kb + a_kof) * 2;
            #pragma unroll
            for (int mt = 0; mt < 5; mt++) {
                ldsm4(ah[mt], sA  + aofs + mt * 16 * ZROWB);
                ldsm4(al[mt], sAl + aofs + mt * 16 * ZROWB);
            }
            uint32_t bofs = b_row * ZROWB + (kb + b_kof) * 2;
            #pragma unroll
            for (int np = 0; np < 2; np++) {
                ldsm4(bh[np], sB  + bofs + np * 16 * ZROWB);
                ldsm4(bl[np], sBl + bofs + np * 16 * ZROWB);
            }
            #pragma unroll
            for (int mt = 0; mt < 5; mt++)
                #pragma unroll
                for (int j = 0; j < 4; j++) {
                    const uint32_t* pbh = &bh[j >> 1][(j & 1) * 2];
                    const uint32_t* pbl = &bl[j >> 1][(j & 1) * 2];
                    mma16816(acc[mt][j], ah[mt], pbh);
                    mma16816(acc[mt][j], ah[mt], pbl);
                    mma16816(acc[mt][j], al[mt], pbh);
                }
        }
        __syncthreads();
    }

    // epilogue: rows = n (x at n==64), cols = a; write bf16 split into Zh/Zl
    #pragma unroll
    for (int mt = 0; mt < 5; mt++) {
        #pragma unroll
        for (int half = 0; half < 2; half++) {
            int r = mt * 16 + (lane >> 2) + half * 8;
            int zr;
            if (r < 64)       zr = 64 + b * NN + r;
            else if (r == 64) zr = b;
            else continue;
            #pragma unroll
            for (int j = 0; j < 4; j++) {
                int col = c * FF + wn + j * 8 + (lane & 3) * 2;
                float v0 = acc[mt][j][half * 2], v1 = acc[mt][j][half * 2 + 1];
                __nv_bfloat16 h0 = __float2bfloat16(v0);
                __nv_bfloat16 h1 = __float2bfloat16(v1);
                __nv_bfloat16 l0 = __float2bfloat16(v0 - __bfloat162float(h0));
                __nv_bfloat16 l1 = __float2bfloat16(v1 - __bfloat162float(h1));
                *(__nv_bfloat162*)(g_Zh + (size_t)zr * KDIM + col) =
                    __nv_bfloat162{h0, h1};
                *(__nv_bfloat162*)(g_Zl + (size_t)zr * KDIM + col) =
                    __nv_bfloat162{l0, l1};
            }
        }
    }
}

// ====================== K7: big GEMM (unchanged, proven) ======================
#define NST 3
#define ROWB 80
#define TILE_B (128 * ROWB)
#define STAGE_B (4 * TILE_B)
#define GEMM_SMEM (NST * STAGE_B)

__device__ __forceinline__ void g_load_stage(char* smembase, int st, int kc,
                                             int tid, int m0, int n0) {
    uint32_t so_base = smem_u32(smembase) + st * STAGE_B;
    #pragma unroll
    for (int t = 0; t < 2; t++) {
        int idx = tid + (t << 8);
        int row = idx >> 2, seg = idx & 3;
        size_t gA = (size_t)(m0 + row) * KDIM + (kc << 5) + (seg << 3);
        size_t gB = (size_t)(n0 + row) * KDIM + (kc << 5) + (seg << 3);
        uint32_t so = so_base + row * ROWB + (seg << 4);
        cp16(so,              g_Zh + gA);
        cp16(so + TILE_B,     g_Zl + gA);
        cp16(so + 2 * TILE_B, g_Wh + gB);
        cp16(so + 3 * TILE_B, g_Wl + gB);
    }
}

__global__ __launch_bounds__(256, 1) void k_gemm_mma(float* __restrict__ out) {
    extern __shared__ char sm[];
    uint32_t sbase = smem_u32(sm);
    int tid = threadIdx.x;
    int lane = tid & 31, wid = tid >> 5;
    int m0 = blockIdx.y << 7, n0 = blockIdx.x << 7;
    int wm = (wid >> 2) << 6;
    int wn = (wid & 3) << 5;

    float c[4][4][4];
    #pragma unroll
    for (int i = 0; i < 4; i++)
        #pragma unroll
        for (int j = 0; j < 4; j++)
            #pragma unroll
            for (int q = 0; q < 4; q++) c[i][j][q] = 0.f;

    int a_row = wm + ((lane >> 3) & 1) * 8 + (lane & 7);
    int a_kof = (lane >> 4) * 8;
    int b_row = wn + ((lane >> 4) & 1) * 8 + (lane & 7);
    int b_kof = ((lane >> 3) & 1) * 8;

    g_load_stage(sm, 0, 0, tid, m0, n0);
    asm volatile("cp.async.commit_group;" ::: "memory");
    g_load_stage(sm, 1, 1, tid, m0, n0);
    asm volatile("cp.async.commit_group;" ::: "memory");

    for (int kc = 0; kc < 64; kc++) {
        asm volatile("cp.async.wait_group 1;" ::: "memory");
        __syncthreads();
        if (kc + 2 < 64) g_load_stage(sm, (kc + 2) % NST, kc + 2, tid, m0, n0);
        asm volatile("cp.async.commit_group;" ::: "memory");

        uint32_t sA  = sbase + (kc % NST) * STAGE_B;
        uint32_t sAl = sA + TILE_B;
        uint32_t sB  = sA + 2 * TILE_B;
        uint32_t sBl = sA + 3 * TILE_B;
        #pragma unroll
        for (int kk = 0; kk < 2; kk++) {
            int kb = kk << 4;
            uint32_t ah[4][4], al[4][4], bh[2][4], bl[2][4];
            uint32_t aofs = a_row * ROWB + (kb + a_kof) * 2;
            #pragma unroll
            for (int mt = 0; mt < 4; mt++) {
                ldsm4(ah[mt], sA  + aofs + mt * 16 * ROWB);
                ldsm4(al[mt], sAl + aofs + mt * 16 * ROWB);
            }
            uint32_t bofs = b_row * ROWB + (kb + b_kof) * 2;
            #pragma unroll
            for (int np = 0; np < 2; np++) {
                ldsm4(bh[np], sB  + bofs + np * 16 * ROWB);
                ldsm4(bl[np], sBl + bofs + np * 16 * ROWB);
            }
            #pragma unroll
            for (int mt = 0; mt < 4; mt++)
                #pragma unroll
                for (int j = 0; j < 4; j++) {
                    const uint32_t* pbh = &bh[j >> 1][(j & 1) * 2];
                    const uint32_t* pbl = &bl[j >> 1][(j & 1) * 2];
                    mma16816(c[mt][j], ah[mt], pbh);
                    mma16816(c[mt][j], ah[mt], pbl);
                    mma16816(c[mt][j], al[mt], pbh);
                }
        }
        __syncthreads();
    }

    #pragma unroll
    for (int mt = 0; mt < 4; mt++) {
        int r0 = m0 + wm + mt * 16 + (lane >> 2);
        #pragma unroll
        for (int j = 0; j < 4; j++) {
            int col = n0 + wn + j * 8 + (lane & 3) * 2;
            if (r0 < MROWS)
                *(float2*)(out + (size_t)r0 * ODIM + col) =
                    make_float2(c[mt][j][0], c[mt][j][1]);
            if (r0 + 8 < MROWS)
                *(float2*)(out + (size_t)(r0 + 8) * ODIM + col) =
                    make_float2(c[mt][j][2], c[mt][j][3]);
        }
    }
}

extern "C" void kernel_launch(void* const* d_in, const int* in_sizes, int n_in,
                              void* d_out, int out_size) {
    const float* x  = (const float*)d_in[0];  // (64,8,256)
    const float* nb = (const float*)d_in[1];  // (64,64,8,256)
    const float* W1 = (const float*)d_in[2];  // (8,256)
    const float* W2 = (const float*)d_in[3];  // (8,256)
    const float* Wc = (const float*)d_in[4];  // (2048,8,256)
    float* out = (float*)d_out;

    static bool attr_set = false;
    if (!attr_set) {
        cudaFuncSetAttribute(k_gemm_mma, cudaFuncAttributeMaxDynamicSharedMemorySize,
                             GEMM_SMEM);
        cudaFuncSetAttribute(k_znx, cudaFuncAttributeMaxDynamicSharedMemorySize,
                             ZNX_SMEM);
        attr_set = true;
    }

    k_wsum<<<1, 256>>>(W1, W2);
    k_cvt_W<<<ODIM, 256>>>(Wc);
    k_cvt_nx<<<dim3(80, BB), 256>>>(x, nb);
    k_s1<<<BB, 256>>>(x);
    k_w<<<BB * NN, 256>>>(nb);
    k_t<<<512, 256>>>(nb);
    k_adj<<<dim3(FF, BB), 256>>>(x);
    k_zero_pad<<<MPAD - MROWS, 256>>>();
    k_znx<<<dim3(CC, BB), 256, ZNX_SMEM>>>();
    k_gemm_mma<<<dim3(16, 33), 256, GEMM_SMEM>>>(out);
}